// round 12
// baseline (speedup 1.0000x reference)
#include <cuda_runtime.h>
#include <stdint.h>

#define Nn 100000
#define Ee 1600000
#define EAd 7
#define Hd 64
#define Ld 32
#define Gg 512
#define Cc 6
#define CH 256   // edges per staged chunk

// ---------------- scratch ----------------
__device__ __align__(256) float g_agg1[Nn];
__device__ __align__(256) float g_h1[Nn * Hd];
__device__ __align__(256) float g_agg2[Nn * Hd];

// ---------------- packed f32x2 helpers ----------------
__device__ __forceinline__ void fma2(unsigned long long& acc, unsigned long long a,
                                     unsigned long long b) {
    asm("fma.rn.f32x2 %0, %1, %2, %0;" : "+l"(acc) : "l"(a), "l"(b));
}
__device__ __forceinline__ unsigned long long pk(float lo, float hi) {
    unsigned long long r;
    asm("mov.b64 %0, {%1, %2};" : "=l"(r) : "f"(lo), "f"(hi));
    return r;
}
__device__ __forceinline__ float hadd2(unsigned long long p) {
    float lo, hi;
    asm("mov.b64 {%0, %1}, %2;" : "=f"(lo), "=f"(hi) : "l"(p));
    return lo + hi;
}
__device__ __forceinline__ void lds_2x64(unsigned long long& v0, unsigned long long& v1,
                                         unsigned saddr) {
    asm volatile("ld.shared.v2.u64 {%0, %1}, [%2];" : "=l"(v0), "=l"(v1) : "r"(saddr));
}

// ---------------- Threefry-2x32 partitionable (JAX >= 0.4.36 default) ----------------
__device__ __forceinline__ float tf_normal(unsigned j) {
    unsigned x0 = 0u;       // counts_hi
    unsigned x1 = j;        // counts_lo
    const unsigned k0 = 0u, k1 = 42u;
    const unsigned k2 = k0 ^ k1 ^ 0x1BD11BDAu;
    x0 += k0; x1 += k1;
    const int R0[4] = {13, 15, 26, 6};
    const int R1[4] = {17, 29, 16, 24};
#pragma unroll
    for (int i = 0; i < 5; i++) {
#pragma unroll
        for (int r = 0; r < 4; r++) {
            int rr = ((i & 1) == 0) ? R0[r] : R1[r];
            x0 += x1;
            x1 = (x1 << rr) | (x1 >> (32 - rr));
            x1 ^= x0;
        }
        unsigned a0 = (i % 3 == 0) ? k1 : (i % 3 == 1) ? k2 : k0;
        unsigned a1 = (i % 3 == 0) ? k2 : (i % 3 == 1) ? k0 : k1;
        x0 += a0;
        x1 += a1 + (unsigned)(i + 1);
    }
    unsigned bits = x0 ^ x1;

    float f = __fadd_rn(__uint_as_float((bits >> 9) | 0x3f800000u), -1.0f);
    const float lo = -0.99999994f;
    float u = __fadd_rn(__fmul_rn(f, 2.0f), lo);
    u = fmaxf(u, lo);

    float w = -log1pf(-u * u);
    float p;
    if (w < 5.0f) {
        w -= 2.5f;
        p = 2.81022636e-08f;
        p = fmaf(p, w, 3.43273939e-07f);
        p = fmaf(p, w, -3.5233877e-06f);
        p = fmaf(p, w, -4.39150654e-06f);
        p = fmaf(p, w, 0.00021858087f);
        p = fmaf(p, w, -0.00125372503f);
        p = fmaf(p, w, -0.00417768164f);
        p = fmaf(p, w, 0.246640727f);
        p = fmaf(p, w, 1.50140941f);
    } else {
        w = sqrtf(w) - 3.0f;
        p = -0.000200214257f;
        p = fmaf(p, w, 0.000100950558f);
        p = fmaf(p, w, 0.00134934322f);
        p = fmaf(p, w, -0.00367342844f);
        p = fmaf(p, w, 0.00573950773f);
        p = fmaf(p, w, -0.0076224613f);
        p = fmaf(p, w, 0.00943887047f);
        p = fmaf(p, w, 1.00167406f);
        p = fmaf(p, w, 2.83297682f);
    }
    return 1.41421356f * (p * u);
}

// ---------------- kernels ----------------
__global__ void k_zero() {
    int i = blockIdx.x * blockDim.x + threadIdx.x;
    const int tot = (Nn + Nn * Hd) / 4;
    if (i < tot) {
        float4 z = make_float4(0.f, 0.f, 0.f, 0.f);
        if (i < Nn / 4) ((float4*)g_agg1)[i] = z;
        else            ((float4*)g_agg2)[i - Nn / 4] = z;
    }
}

// conv1 edge: 4 edges/thread; ea via 7x LDG.128, ei via 2x int4
__global__ void k_conv1_edge(const float* __restrict__ x, const int* __restrict__ ei,
                             const float* __restrict__ ea, const float* __restrict__ We1,
                             const float* __restrict__ be1) {
    int g4 = blockIdx.x * blockDim.x + threadIdx.x;
    if (g4 >= Ee / 4) return;
    int e0 = g4 * 4;

    float w[EAd];
#pragma unroll
    for (int i = 0; i < EAd; i++) w[i] = __ldg(We1 + i);
    float be = __ldg(be1);

    float A[28];
    const float4* ap = (const float4*)(ea + (long long)e0 * EAd);
#pragma unroll
    for (int i = 0; i < 7; i++) *((float4*)&A[i * 4]) = __ldg(ap + i);

    int4 ss = *(const int4*)(ei + e0);
    int4 dd = *(const int4*)(ei + Ee + e0);
    int sv[4] = {ss.x, ss.y, ss.z, ss.w};
    int dv[4] = {dd.x, dd.y, dd.z, dd.w};

#pragma unroll
    for (int j = 0; j < 4; j++) {
        float acc = be;
#pragma unroll
        for (int i = 0; i < EAd; i++) acc = fmaf(A[j * EAd + i], w[i], acc);
        float m = fmaxf(__ldg(x + sv[j]) + acc, 0.f);
        atomicAdd(&g_agg1[dv[j]], m);
    }
}

// conv1 node MLP: 16 nodes/block, 128 threads, packed f32x2 inner loop
__global__ void k_conv1_mlp(const float* __restrict__ x, const float* __restrict__ W11,
                            const float* __restrict__ b11, const float* __restrict__ W12,
                            const float* __restrict__ b12, const float* __restrict__ eps1) {
    __shared__ float tS[16 * Hd];
    int k = threadIdx.x & 63;
    int hh = threadIdx.x >> 6;   // 0/1
    unsigned long long wp[Hd / 2];
#pragma unroll
    for (int jh = 0; jh < Hd / 2; jh++)
        wp[jh] = pk(__ldg(W12 + (2 * jh) * Hd + k), __ldg(W12 + (2 * jh + 1) * Hd + k));

    int n0 = blockIdx.x * 16;
    int rb = hh * 8;
    int nb = n0 + rb;
    float ep = 1.f + *eps1;
    float w11k = __ldg(W11 + k), b11k = __ldg(b11 + k);
#pragma unroll
    for (int i = 0; i < 8; i++) {
        float a = ep * __ldg(x + nb + i) + g_agg1[nb + i];
        tS[(rb + i) * Hd + k] = fmaxf(a * w11k + b11k, 0.f);
    }
    __syncthreads();
    unsigned sb = (unsigned)__cvta_generic_to_shared(tS);
    float bk = __ldg(b12 + k);
#pragma unroll
    for (int i = 0; i < 8; i++) {
        unsigned long long accp = pk(bk, 0.f);
        unsigned a0 = sb + (rb + i) * Hd * 4;
#pragma unroll
        for (int jq = 0; jq < Hd / 4; jq++) {
            unsigned long long v0, v1;
            lds_2x64(v0, v1, a0 + jq * 16);
            fma2(accp, v0, wp[2 * jq]);
            fma2(accp, v1, wp[2 * jq + 1]);
        }
        g_h1[(long long)(nb + i) * Hd + k] = fmaxf(hadd2(accp), 0.f);
    }
}

// conv2 edge v7: SMEM-staged ea/ei chunks + 16 lanes/edge + h1 prefetch pipeline
__global__ void __launch_bounds__(256, 4) k_conv2_edge(
        const int* __restrict__ ei, const float* __restrict__ ea,
        const float* __restrict__ We2, const float* __restrict__ be2) {
    __shared__ float sea[CH * EAd];  // 7168 B
    __shared__ int ssrc[CH];         // 1024 B
    __shared__ int sdst[CH];         // 1024 B
    int t = threadIdx.x;  // 256
    int lane = t & 15;
    int grp = t >> 4;     // 16 groups/block, 16 edges each
    int c0 = lane * 4;
    float4 wr[EAd];
#pragma unroll
    for (int i = 0; i < EAd; i++) wr[i] = *(const float4*)&We2[i * Hd + c0];
    float4 br = *(const float4*)&be2[c0];

    const int step = gridDim.x * CH;
    for (int base = blockIdx.x * CH; base < Ee; base += step) {
        __syncthreads();  // protect previous chunk's SMEM reads
        {
            const float4* gp = (const float4*)(ea + (long long)base * EAd);
#pragma unroll
            for (int i = t; i < CH * EAd / 4; i += 256)
                ((float4*)sea)[i] = __ldg(gp + i);
            if (t < CH / 4) {
                ((int4*)ssrc)[t] = __ldg((const int4*)(ei + base) + t);
                ((int4*)sdst)[t] = __ldg((const int4*)(ei + Ee + base) + t);
            }
        }
        __syncthreads();

        int eb = grp * 16;
        int d = sdst[eb];
        float4 h;
        {
            int s = ssrc[eb];
            h = *(const float4*)(g_h1 + (long long)s * Hd + c0);
        }
#pragma unroll
        for (int j = 0; j < 16; j++) {
            int dn = 0;
            float4 hn = h;
            if (j + 1 < 16) {
                int sn = ssrc[eb + j + 1];
                dn = sdst[eb + j + 1];
                hn = *(const float4*)(g_h1 + (long long)sn * Hd + c0);
            }
            const float* aa = &sea[(eb + j) * EAd];
            float4 p = br;
#pragma unroll
            for (int i = 0; i < EAd; i++) {
                float av = aa[i];
                p.x = fmaf(av, wr[i].x, p.x);
                p.y = fmaf(av, wr[i].y, p.y);
                p.z = fmaf(av, wr[i].z, p.z);
                p.w = fmaf(av, wr[i].w, p.w);
            }
            float4 m;
            m.x = fmaxf(h.x + p.x, 0.f);
            m.y = fmaxf(h.y + p.y, 0.f);
            m.z = fmaxf(h.z + p.z, 0.f);
            m.w = fmaxf(h.w + p.w, 0.f);
            float* dst = g_agg2 + (long long)d * Hd + c0;
            asm volatile("red.global.add.v4.f32 [%0], {%1,%2,%3,%4};"
                         :: "l"(dst), "f"(m.x), "f"(m.y), "f"(m.z), "f"(m.w) : "memory");
            d = dn; h = hn;
        }
    }
}

// conv2 node MLP + heads: 16 nodes/block, 128 threads, packed f32x2 inner loops
__global__ void k_conv2_mlp(const float* __restrict__ W21, const float* __restrict__ b21,
                            const float* __restrict__ W22, const float* __restrict__ b22,
                            const float* __restrict__ eps2, const float* __restrict__ Wmu,
                            const float* __restrict__ bmu, const float* __restrict__ Wlv,
                            const float* __restrict__ blv, float* __restrict__ outz,
                            float* __restrict__ outmu, float* __restrict__ outlv) {
    __shared__ float bufA[16 * Hd];
    __shared__ float bufB[16 * Hd];
    int k = threadIdx.x & 63;
    int hh = threadIdx.x >> 6;   // 0/1
    int n0 = blockIdx.x * 16;
    int rb = hh * 8;             // row base in buffers
    int nb = n0 + rb;
    float ep = 1.f + *eps2;
    unsigned sbA = (unsigned)__cvta_generic_to_shared(bufA);
    unsigned sbB = (unsigned)__cvta_generic_to_shared(bufB);

    unsigned long long wp[Hd / 2];
#pragma unroll
    for (int jh = 0; jh < Hd / 2; jh++)
        wp[jh] = pk(__ldg(W21 + (2 * jh) * Hd + k), __ldg(W21 + (2 * jh + 1) * Hd + k));

#pragma unroll
    for (int i = 0; i < 8; i++) {
        long long o = (long long)(nb + i) * Hd + k;
        bufA[(rb + i) * Hd + k] = ep * g_h1[o] + g_agg2[o];
    }
    __syncthreads();

    // stage 1: bufB = relu(bufA @ W21 + b21)
    {
        float b = __ldg(b21 + k);
#pragma unroll
        for (int i = 0; i < 8; i++) {
            unsigned long long accp = pk(b, 0.f);
            unsigned a0 = sbA + (rb + i) * Hd * 4;
#pragma unroll
            for (int jq = 0; jq < Hd / 4; jq++) {
                unsigned long long v0, v1;
                lds_2x64(v0, v1, a0 + jq * 16);
                fma2(accp, v0, wp[2 * jq]);
                fma2(accp, v1, wp[2 * jq + 1]);
            }
            bufB[(rb + i) * Hd + k] = fmaxf(hadd2(accp), 0.f);
        }
    }
#pragma unroll
    for (int jh = 0; jh < Hd / 2; jh++)
        wp[jh] = pk(__ldg(W22 + (2 * jh) * Hd + k), __ldg(W22 + (2 * jh + 1) * Hd + k));
    __syncthreads();

    // stage 2: bufA = relu(bufB @ W22 + b22)  (h2)
    {
        float b = __ldg(b22 + k);
        float h2v[8];
#pragma unroll
        for (int i = 0; i < 8; i++) {
            unsigned long long accp = pk(b, 0.f);
            unsigned a0 = sbB + (rb + i) * Hd * 4;
#pragma unroll
            for (int jq = 0; jq < Hd / 4; jq++) {
                unsigned long long v0, v1;
                lds_2x64(v0, v1, a0 + jq * 16);
                fma2(accp, v0, wp[2 * jq]);
                fma2(accp, v1, wp[2 * jq + 1]);
            }
            h2v[i] = fmaxf(hadd2(accp), 0.f);
        }
        __syncthreads();
#pragma unroll
        for (int i = 0; i < 8; i++) bufA[(rb + i) * Hd + k] = h2v[i];
    }

    // heads
    int l = k & 31;
    const float* Wh = (k < 32) ? Wmu : Wlv;
#pragma unroll
    for (int jh = 0; jh < Hd / 2; jh++)
        wp[jh] = pk(__ldg(Wh + (2 * jh) * Ld + l), __ldg(Wh + (2 * jh + 1) * Ld + l));
    __syncthreads();

    {
        float b = (k < 32) ? __ldg(bmu + l) : __ldg(blv + l);
        float* oph = (k < 32) ? outmu : outlv;
#pragma unroll
        for (int i = 0; i < 8; i++) {
            unsigned long long accp = pk(b, 0.f);
            unsigned a0 = sbA + (rb + i) * Hd * 4;
#pragma unroll
            for (int jq = 0; jq < Hd / 4; jq++) {
                unsigned long long v0, v1;
                lds_2x64(v0, v1, a0 + jq * 16);
                fma2(accp, v0, wp[2 * jq]);
                fma2(accp, v1, wp[2 * jq + 1]);
            }
            float acc = hadd2(accp);
            bufB[(rb + i) * Hd + k] = acc;
            oph[(long long)(nb + i) * Ld + l] = acc;
        }
    }
    __syncthreads();

    if (k < 32) {
#pragma unroll
        for (int i = 0; i < 8; i++) {
            float mu = bufB[(rb + i) * Hd + k];
            float lv = bufB[(rb + i) * Hd + 32 + k];
            unsigned j = (unsigned)((nb + i) * Ld + k);
            float z = mu + tf_normal(j) * expf(0.5f * lv);
            outz[(long long)(nb + i) * Ld + k] = z;
        }
    }
}

// pooling + classifier: 128 threads (4 warps stride the node range)
__global__ void k_pool(const float* __restrict__ z, const int* __restrict__ batch,
                       const float* __restrict__ Wc, const float* __restrict__ bc,
                       float* __restrict__ logits) {
    int g = blockIdx.x;
    int k = threadIdx.x & 31;   // column
    int w = threadIdx.x >> 5;   // warp 0..3
    __shared__ float part[4 * Ld];
    __shared__ float emb[Ld];
    __shared__ int bounds[2];
    if (threadIdx.x < 2) {
        int target = g + threadIdx.x;
        int lo = 0, hi = Nn;
        while (lo < hi) {
            int mid = (lo + hi) >> 1;
            if (batch[mid] < target) lo = mid + 1; else hi = mid;
        }
        bounds[threadIdx.x] = lo;
    }
    __syncthreads();
    int s = bounds[0], e = bounds[1];
    float acc = 0.f;
    for (int n = s + w; n < e; n += 4) acc += z[(long long)n * Ld + k];
    part[w * Ld + k] = acc;
    __syncthreads();
    if (w == 0) {
        float tot = part[k] + part[Ld + k] + part[2 * Ld + k] + part[3 * Ld + k];
        float cnt = (float)(e - s);
        emb[k] = tot / fmaxf(cnt, 1.f);
    }
    __syncthreads();
    if (threadIdx.x < Cc) {
        float o = __ldg(bc + threadIdx.x);
#pragma unroll
        for (int l = 0; l < Ld; l++) o += emb[l] * __ldg(Wc + l * Cc + threadIdx.x);
        logits[g * Cc + threadIdx.x] = o;
    }
}

// ---------------- launcher ----------------
extern "C" void kernel_launch(void* const* d_in, const int* in_sizes, int n_in,
                              void* d_out, int out_size) {
    const float* x     = (const float*)d_in[0];
    const int*   ei    = (const int*)d_in[1];
    const float* ea    = (const float*)d_in[2];
    const int*   batch = (const int*)d_in[3];
    const float* We1 = (const float*)d_in[4];
    const float* be1 = (const float*)d_in[5];
    const float* W11 = (const float*)d_in[6];
    const float* b11 = (const float*)d_in[7];
    const float* W12 = (const float*)d_in[8];
    const float* b12 = (const float*)d_in[9];
    const float* eps1 = (const float*)d_in[10];
    const float* We2 = (const float*)d_in[11];
    const float* be2 = (const float*)d_in[12];
    const float* W21 = (const float*)d_in[13];
    const float* b21 = (const float*)d_in[14];
    const float* W22 = (const float*)d_in[15];
    const float* b22 = (const float*)d_in[16];
    const float* eps2 = (const float*)d_in[17];
    const float* Wmu = (const float*)d_in[18];
    const float* bmu = (const float*)d_in[19];
    const float* Wlv = (const float*)d_in[20];
    const float* blv = (const float*)d_in[21];
    const float* Wc  = (const float*)d_in[22];
    const float* bc  = (const float*)d_in[23];

    float* out = (float*)d_out;
    float* dz  = out;
    float* dmu = out + (size_t)Nn * Ld;
    float* dlv = out + (size_t)2 * Nn * Ld;
    float* dlg = out + (size_t)3 * Nn * Ld;

    const int ztot = (Nn + Nn * Hd) / 4;
    k_zero<<<(ztot + 255) / 256, 256>>>();
    k_conv1_edge<<<(Ee / 4 + 255) / 256, 256>>>(x, ei, ea, We1, be1);
    k_conv1_mlp<<<Nn / 16, 128>>>(x, W11, b11, W12, b12, eps1);
    k_conv2_edge<<<592, 256>>>(ei, ea, We2, be2);
    k_conv2_mlp<<<Nn / 16, 128>>>(W21, b21, W22, b22, eps2, Wmu, bmu, Wlv, blv, dz, dmu, dlv);
    k_pool<<<Gg, 128>>>(dz, batch, Wc, bc, dlg);
}

// round 13
// speedup vs baseline: 1.0363x; 1.0363x over previous
#include <cuda_runtime.h>
#include <stdint.h>

#define Nn 100000
#define Ee 1600000
#define EAd 7
#define Hd 64
#define Ld 32
#define Gg 512
#define Cc 6
#define CH 256   // edges per staged chunk

// ---------------- scratch ----------------
__device__ __align__(256) float g_agg1[Nn];
__device__ __align__(256) float g_h1[Nn * Hd];
__device__ __align__(256) float g_agg2[Nn * Hd];

// ---------------- packed f32x2 helpers ----------------
__device__ __forceinline__ void fma2(unsigned long long& acc, unsigned long long a,
                                     unsigned long long b) {
    asm("fma.rn.f32x2 %0, %1, %2, %0;" : "+l"(acc) : "l"(a), "l"(b));
}
__device__ __forceinline__ unsigned long long pk(float lo, float hi) {
    unsigned long long r;
    asm("mov.b64 %0, {%1, %2};" : "=l"(r) : "f"(lo), "f"(hi));
    return r;
}
__device__ __forceinline__ float hadd2(unsigned long long p) {
    float lo, hi;
    asm("mov.b64 {%0, %1}, %2;" : "=f"(lo), "=f"(hi) : "l"(p));
    return lo + hi;
}
__device__ __forceinline__ void lds_2x64(unsigned long long& v0, unsigned long long& v1,
                                         unsigned saddr) {
    asm volatile("ld.shared.v2.u64 {%0, %1}, [%2];" : "=l"(v0), "=l"(v1) : "r"(saddr));
}

// ---------------- Threefry-2x32 partitionable (JAX >= 0.4.36 default) ----------------
__device__ __forceinline__ float tf_normal(unsigned j) {
    unsigned x0 = 0u;       // counts_hi
    unsigned x1 = j;        // counts_lo
    const unsigned k0 = 0u, k1 = 42u;
    const unsigned k2 = k0 ^ k1 ^ 0x1BD11BDAu;
    x0 += k0; x1 += k1;
    const int R0[4] = {13, 15, 26, 6};
    const int R1[4] = {17, 29, 16, 24};
#pragma unroll
    for (int i = 0; i < 5; i++) {
#pragma unroll
        for (int r = 0; r < 4; r++) {
            int rr = ((i & 1) == 0) ? R0[r] : R1[r];
            x0 += x1;
            x1 = (x1 << rr) | (x1 >> (32 - rr));
            x1 ^= x0;
        }
        unsigned a0 = (i % 3 == 0) ? k1 : (i % 3 == 1) ? k2 : k0;
        unsigned a1 = (i % 3 == 0) ? k2 : (i % 3 == 1) ? k0 : k1;
        x0 += a0;
        x1 += a1 + (unsigned)(i + 1);
    }
    unsigned bits = x0 ^ x1;

    float f = __fadd_rn(__uint_as_float((bits >> 9) | 0x3f800000u), -1.0f);
    const float lo = -0.99999994f;
    float u = __fadd_rn(__fmul_rn(f, 2.0f), lo);
    u = fmaxf(u, lo);

    float w = -log1pf(-u * u);
    float p;
    if (w < 5.0f) {
        w -= 2.5f;
        p = 2.81022636e-08f;
        p = fmaf(p, w, 3.43273939e-07f);
        p = fmaf(p, w, -3.5233877e-06f);
        p = fmaf(p, w, -4.39150654e-06f);
        p = fmaf(p, w, 0.00021858087f);
        p = fmaf(p, w, -0.00125372503f);
        p = fmaf(p, w, -0.00417768164f);
        p = fmaf(p, w, 0.246640727f);
        p = fmaf(p, w, 1.50140941f);
    } else {
        w = sqrtf(w) - 3.0f;
        p = -0.000200214257f;
        p = fmaf(p, w, 0.000100950558f);
        p = fmaf(p, w, 0.00134934322f);
        p = fmaf(p, w, -0.00367342844f);
        p = fmaf(p, w, 0.00573950773f);
        p = fmaf(p, w, -0.0076224613f);
        p = fmaf(p, w, 0.00943887047f);
        p = fmaf(p, w, 1.00167406f);
        p = fmaf(p, w, 2.83297682f);
    }
    return 1.41421356f * (p * u);
}

// ---------------- kernels ----------------
__global__ void k_zero() {
    int i = blockIdx.x * blockDim.x + threadIdx.x;
    const int tot = (Nn + Nn * Hd) / 4;
    if (i < tot) {
        float4 z = make_float4(0.f, 0.f, 0.f, 0.f);
        if (i < Nn / 4) ((float4*)g_agg1)[i] = z;
        else            ((float4*)g_agg2)[i - Nn / 4] = z;
    }
}

// conv1 edge: 4 edges/thread; ea via 7x LDG.128, ei via 2x int4
__global__ void k_conv1_edge(const float* __restrict__ x, const int* __restrict__ ei,
                             const float* __restrict__ ea, const float* __restrict__ We1,
                             const float* __restrict__ be1) {
    int g4 = blockIdx.x * blockDim.x + threadIdx.x;
    if (g4 >= Ee / 4) return;
    int e0 = g4 * 4;

    float w[EAd];
#pragma unroll
    for (int i = 0; i < EAd; i++) w[i] = __ldg(We1 + i);
    float be = __ldg(be1);

    float A[28];
    const float4* ap = (const float4*)(ea + (long long)e0 * EAd);
#pragma unroll
    for (int i = 0; i < 7; i++) *((float4*)&A[i * 4]) = __ldg(ap + i);

    int4 ss = *(const int4*)(ei + e0);
    int4 dd = *(const int4*)(ei + Ee + e0);
    int sv[4] = {ss.x, ss.y, ss.z, ss.w};
    int dv[4] = {dd.x, dd.y, dd.z, dd.w};

#pragma unroll
    for (int j = 0; j < 4; j++) {
        float acc = be;
#pragma unroll
        for (int i = 0; i < EAd; i++) acc = fmaf(A[j * EAd + i], w[i], acc);
        float m = fmaxf(__ldg(x + sv[j]) + acc, 0.f);
        atomicAdd(&g_agg1[dv[j]], m);
    }
}

// conv1 node MLP: 16 nodes/block, 128 threads, f32x2 with 8 interleaved accumulators
__global__ void k_conv1_mlp(const float* __restrict__ x, const float* __restrict__ W11,
                            const float* __restrict__ b11, const float* __restrict__ W12,
                            const float* __restrict__ b12, const float* __restrict__ eps1) {
    __shared__ float tS[16 * Hd];
    int k = threadIdx.x & 63;
    int hh = threadIdx.x >> 6;   // 0/1
    unsigned long long wp[Hd / 2];
#pragma unroll
    for (int jh = 0; jh < Hd / 2; jh++)
        wp[jh] = pk(__ldg(W12 + (2 * jh) * Hd + k), __ldg(W12 + (2 * jh + 1) * Hd + k));

    int n0 = blockIdx.x * 16;
    int rb = hh * 8;
    int nb = n0 + rb;
    float ep = 1.f + *eps1;
    float w11k = __ldg(W11 + k), b11k = __ldg(b11 + k);
#pragma unroll
    for (int i = 0; i < 8; i++) {
        float a = ep * __ldg(x + nb + i) + g_agg1[nb + i];
        tS[(rb + i) * Hd + k] = fmaxf(a * w11k + b11k, 0.f);
    }
    __syncthreads();
    unsigned sb = (unsigned)__cvta_generic_to_shared(tS) + rb * Hd * 4;
    float bk = __ldg(b12 + k);
    unsigned long long accp[8];
#pragma unroll
    for (int i = 0; i < 8; i++) accp[i] = pk(bk, 0.f);
#pragma unroll
    for (int jq = 0; jq < Hd / 4; jq++) {
#pragma unroll
        for (int i = 0; i < 8; i++) {
            unsigned long long v0, v1;
            lds_2x64(v0, v1, sb + i * Hd * 4 + jq * 16);
            fma2(accp[i], v0, wp[2 * jq]);
            fma2(accp[i], v1, wp[2 * jq + 1]);
        }
    }
#pragma unroll
    for (int i = 0; i < 8; i++)
        g_h1[(long long)(nb + i) * Hd + k] = fmaxf(hadd2(accp[i]), 0.f);
}

// conv2 edge v7: SMEM-staged ea/ei chunks + 16 lanes/edge + h1 prefetch pipeline
__global__ void __launch_bounds__(256, 4) k_conv2_edge(
        const int* __restrict__ ei, const float* __restrict__ ea,
        const float* __restrict__ We2, const float* __restrict__ be2) {
    __shared__ float sea[CH * EAd];  // 7168 B
    __shared__ int ssrc[CH];         // 1024 B
    __shared__ int sdst[CH];         // 1024 B
    int t = threadIdx.x;  // 256
    int lane = t & 15;
    int grp = t >> 4;     // 16 groups/block, 16 edges each
    int c0 = lane * 4;
    float4 wr[EAd];
#pragma unroll
    for (int i = 0; i < EAd; i++) wr[i] = *(const float4*)&We2[i * Hd + c0];
    float4 br = *(const float4*)&be2[c0];

    const int step = gridDim.x * CH;
    for (int base = blockIdx.x * CH; base < Ee; base += step) {
        __syncthreads();  // protect previous chunk's SMEM reads
        {
            const float4* gp = (const float4*)(ea + (long long)base * EAd);
#pragma unroll
            for (int i = t; i < CH * EAd / 4; i += 256)
                ((float4*)sea)[i] = __ldg(gp + i);
            if (t < CH / 4) {
                ((int4*)ssrc)[t] = __ldg((const int4*)(ei + base) + t);
                ((int4*)sdst)[t] = __ldg((const int4*)(ei + Ee + base) + t);
            }
        }
        __syncthreads();

        int eb = grp * 16;
        int d = sdst[eb];
        float4 h;
        {
            int s = ssrc[eb];
            h = *(const float4*)(g_h1 + (long long)s * Hd + c0);
        }
#pragma unroll
        for (int j = 0; j < 16; j++) {
            int dn = 0;
            float4 hn = h;
            if (j + 1 < 16) {
                int sn = ssrc[eb + j + 1];
                dn = sdst[eb + j + 1];
                hn = *(const float4*)(g_h1 + (long long)sn * Hd + c0);
            }
            const float* aa = &sea[(eb + j) * EAd];
            float4 p = br;
#pragma unroll
            for (int i = 0; i < EAd; i++) {
                float av = aa[i];
                p.x = fmaf(av, wr[i].x, p.x);
                p.y = fmaf(av, wr[i].y, p.y);
                p.z = fmaf(av, wr[i].z, p.z);
                p.w = fmaf(av, wr[i].w, p.w);
            }
            float4 m;
            m.x = fmaxf(h.x + p.x, 0.f);
            m.y = fmaxf(h.y + p.y, 0.f);
            m.z = fmaxf(h.z + p.z, 0.f);
            m.w = fmaxf(h.w + p.w, 0.f);
            float* dst = g_agg2 + (long long)d * Hd + c0;
            asm volatile("red.global.add.v4.f32 [%0], {%1,%2,%3,%4};"
                         :: "l"(dst), "f"(m.x), "f"(m.y), "f"(m.z), "f"(m.w) : "memory");
            d = dn; h = hn;
        }
    }
}

// conv2 node MLP + heads: 16 nodes/block, 128 threads, f32x2 interleaved accumulators
__global__ void k_conv2_mlp(const float* __restrict__ W21, const float* __restrict__ b21,
                            const float* __restrict__ W22, const float* __restrict__ b22,
                            const float* __restrict__ eps2, const float* __restrict__ Wmu,
                            const float* __restrict__ bmu, const float* __restrict__ Wlv,
                            const float* __restrict__ blv, float* __restrict__ outz,
                            float* __restrict__ outmu, float* __restrict__ outlv) {
    __shared__ float bufA[16 * Hd];
    __shared__ float bufB[16 * Hd];
    int k = threadIdx.x & 63;
    int hh = threadIdx.x >> 6;   // 0/1
    int n0 = blockIdx.x * 16;
    int rb = hh * 8;             // row base in buffers
    int nb = n0 + rb;
    float ep = 1.f + *eps2;
    unsigned sbA = (unsigned)__cvta_generic_to_shared(bufA) + rb * Hd * 4;
    unsigned sbB = (unsigned)__cvta_generic_to_shared(bufB) + rb * Hd * 4;

    unsigned long long wp[Hd / 2];
    unsigned long long accp[8];
#pragma unroll
    for (int jh = 0; jh < Hd / 2; jh++)
        wp[jh] = pk(__ldg(W21 + (2 * jh) * Hd + k), __ldg(W21 + (2 * jh + 1) * Hd + k));

#pragma unroll
    for (int i = 0; i < 8; i++) {
        long long o = (long long)(nb + i) * Hd + k;
        bufA[(rb + i) * Hd + k] = ep * g_h1[o] + g_agg2[o];
    }
    __syncthreads();

    // stage 1: bufB = relu(bufA @ W21 + b21)
    {
        float b = __ldg(b21 + k);
#pragma unroll
        for (int i = 0; i < 8; i++) accp[i] = pk(b, 0.f);
#pragma unroll
        for (int jq = 0; jq < Hd / 4; jq++) {
#pragma unroll
            for (int i = 0; i < 8; i++) {
                unsigned long long v0, v1;
                lds_2x64(v0, v1, sbA + i * Hd * 4 + jq * 16);
                fma2(accp[i], v0, wp[2 * jq]);
                fma2(accp[i], v1, wp[2 * jq + 1]);
            }
        }
#pragma unroll
        for (int i = 0; i < 8; i++)
            bufB[(rb + i) * Hd + k] = fmaxf(hadd2(accp[i]), 0.f);
    }
#pragma unroll
    for (int jh = 0; jh < Hd / 2; jh++)
        wp[jh] = pk(__ldg(W22 + (2 * jh) * Hd + k), __ldg(W22 + (2 * jh + 1) * Hd + k));
    __syncthreads();

    // stage 2: bufA = relu(bufB @ W22 + b22)  (h2)
    {
        float b = __ldg(b22 + k);
#pragma unroll
        for (int i = 0; i < 8; i++) accp[i] = pk(b, 0.f);
#pragma unroll
        for (int jq = 0; jq < Hd / 4; jq++) {
#pragma unroll
            for (int i = 0; i < 8; i++) {
                unsigned long long v0, v1;
                lds_2x64(v0, v1, sbB + i * Hd * 4 + jq * 16);
                fma2(accp[i], v0, wp[2 * jq]);
                fma2(accp[i], v1, wp[2 * jq + 1]);
            }
        }
        __syncthreads();
#pragma unroll
        for (int i = 0; i < 8; i++)
            bufA[(rb + i) * Hd + k] = fmaxf(hadd2(accp[i]), 0.f);
    }

    // heads
    int l = k & 31;
    const float* Wh = (k < 32) ? Wmu : Wlv;
#pragma unroll
    for (int jh = 0; jh < Hd / 2; jh++)
        wp[jh] = pk(__ldg(Wh + (2 * jh) * Ld + l), __ldg(Wh + (2 * jh + 1) * Ld + l));
    __syncthreads();

    {
        float b = (k < 32) ? __ldg(bmu + l) : __ldg(blv + l);
        float* oph = (k < 32) ? outmu : outlv;
#pragma unroll
        for (int i = 0; i < 8; i++) accp[i] = pk(b, 0.f);
#pragma unroll
        for (int jq = 0; jq < Hd / 4; jq++) {
#pragma unroll
            for (int i = 0; i < 8; i++) {
                unsigned long long v0, v1;
                lds_2x64(v0, v1, sbA + i * Hd * 4 + jq * 16);
                fma2(accp[i], v0, wp[2 * jq]);
                fma2(accp[i], v1, wp[2 * jq + 1]);
            }
        }
#pragma unroll
        for (int i = 0; i < 8; i++) {
            float acc = hadd2(accp[i]);
            bufB[(rb + i) * Hd + k] = acc;
            oph[(long long)(nb + i) * Ld + l] = acc;
        }
    }
    __syncthreads();

    if (k < 32) {
#pragma unroll
        for (int i = 0; i < 8; i++) {
            float mu = bufB[(rb + i) * Hd + k];
            float lv = bufB[(rb + i) * Hd + 32 + k];
            unsigned j = (unsigned)((nb + i) * Ld + k);
            float z = mu + tf_normal(j) * expf(0.5f * lv);
            outz[(long long)(nb + i) * Ld + k] = z;
        }
    }
}

// pooling + classifier: 128 threads (4 warps stride the node range)
__global__ void k_pool(const float* __restrict__ z, const int* __restrict__ batch,
                       const float* __restrict__ Wc, const float* __restrict__ bc,
                       float* __restrict__ logits) {
    int g = blockIdx.x;
    int k = threadIdx.x & 31;   // column
    int w = threadIdx.x >> 5;   // warp 0..3
    __shared__ float part[4 * Ld];
    __shared__ float emb[Ld];
    __shared__ int bounds[2];
    if (threadIdx.x < 2) {
        int target = g + threadIdx.x;
        int lo = 0, hi = Nn;
        while (lo < hi) {
            int mid = (lo + hi) >> 1;
            if (batch[mid] < target) lo = mid + 1; else hi = mid;
        }
        bounds[threadIdx.x] = lo;
    }
    __syncthreads();
    int s = bounds[0], e = bounds[1];
    float acc = 0.f;
    for (int n = s + w; n < e; n += 4) acc += z[(long long)n * Ld + k];
    part[w * Ld + k] = acc;
    __syncthreads();
    if (w == 0) {
        float tot = part[k] + part[Ld + k] + part[2 * Ld + k] + part[3 * Ld + k];
        float cnt = (float)(e - s);
        emb[k] = tot / fmaxf(cnt, 1.f);
    }
    __syncthreads();
    if (threadIdx.x < Cc) {
        float o = __ldg(bc + threadIdx.x);
#pragma unroll
        for (int l = 0; l < Ld; l++) o += emb[l] * __ldg(Wc + l * Cc + threadIdx.x);
        logits[g * Cc + threadIdx.x] = o;
    }
}

// ---------------- launcher ----------------
extern "C" void kernel_launch(void* const* d_in, const int* in_sizes, int n_in,
                              void* d_out, int out_size) {
    const float* x     = (const float*)d_in[0];
    const int*   ei    = (const int*)d_in[1];
    const float* ea    = (const float*)d_in[2];
    const int*   batch = (const int*)d_in[3];
    const float* We1 = (const float*)d_in[4];
    const float* be1 = (const float*)d_in[5];
    const float* W11 = (const float*)d_in[6];
    const float* b11 = (const float*)d_in[7];
    const float* W12 = (const float*)d_in[8];
    const float* b12 = (const float*)d_in[9];
    const float* eps1 = (const float*)d_in[10];
    const float* We2 = (const float*)d_in[11];
    const float* be2 = (const float*)d_in[12];
    const float* W21 = (const float*)d_in[13];
    const float* b21 = (const float*)d_in[14];
    const float* W22 = (const float*)d_in[15];
    const float* b22 = (const float*)d_in[16];
    const float* eps2 = (const float*)d_in[17];
    const float* Wmu = (const float*)d_in[18];
    const float* bmu = (const float*)d_in[19];
    const float* Wlv = (const float*)d_in[20];
    const float* blv = (const float*)d_in[21];
    const float* Wc  = (const float*)d_in[22];
    const float* bc  = (const float*)d_in[23];

    float* out = (float*)d_out;
    float* dz  = out;
    float* dmu = out + (size_t)Nn * Ld;
    float* dlv = out + (size_t)2 * Nn * Ld;
    float* dlg = out + (size_t)3 * Nn * Ld;

    const int ztot = (Nn + Nn * Hd) / 4;
    k_zero<<<(ztot + 255) / 256, 256>>>();
    k_conv1_edge<<<(Ee / 4 + 255) / 256, 256>>>(x, ei, ea, We1, be1);
    k_conv1_mlp<<<Nn / 16, 128>>>(x, W11, b11, W12, b12, eps1);
    k_conv2_edge<<<592, 256>>>(ei, ea, We2, be2);
    k_conv2_mlp<<<Nn / 16, 128>>>(W21, b21, W22, b22, eps2, Wmu, bmu, Wlv, blv, dz, dmu, dlv);
    k_pool<<<Gg, 128>>>(dz, batch, Wc, bc, dlg);
}